// round 1
// baseline (speedup 1.0000x reference)
#include <cuda_runtime.h>
#include <float.h>

#define NB 2048
#define NS 200
#define ND 64
#define NH 4
#define NH1 64
#define NH2 32
#define NF 256
#define KST 209   // transposed keys row stride (odd -> conflict-free both access patterns)

// Combined layer-1 weights (built once per launch by prep_kernel; cheap, deterministic)
__device__ float g_W1a[NH*ND*NH1];  // Wk + Wd   (keys part)
__device__ float g_W1b[NH*ND*NH1];  // Wkq       (keys*q part)
__device__ float g_W1c[NH*ND*NH1];  // Wq - Wd   (per-batch bias part)

__global__ void prep_kernel(const float* __restrict__ W1) {
    int idx = blockIdx.x * blockDim.x + threadIdx.x;   // over NH*ND*NH1 = 16384
    if (idx >= NH*ND*NH1) return;
    int j = idx & 63;
    int i = (idx >> 6) & 63;
    int h = idx >> 12;
    const float* w = W1 + h*NF*NH1;
    float wk  = w[(i      )*NH1 + j];
    float wq  = w[(64 + i )*NH1 + j];
    float wkq = w[(128 + i)*NH1 + j];
    float wd  = w[(192 + i)*NH1 + j];
    g_W1a[idx] = wk + wd;
    g_W1b[idx] = wkq;
    g_W1c[idx] = wq - wd;
}

// ---- packed f32x2 helpers (Blackwell FFMA2 path: 2x fp32 FMA throughput) ----
__device__ __forceinline__ void ffma2(unsigned long long &d, unsigned long long a, unsigned long long b) {
    asm("fma.rn.f32x2 %0, %1, %2, %0;" : "+l"(d) : "l"(a), "l"(b));
}
__device__ __forceinline__ unsigned long long bcast2(float x) {
    unsigned long long r;
    asm("mov.b64 %0, {%1, %1};" : "=l"(r) : "f"(x));
    return r;
}
__device__ __forceinline__ unsigned long long pack2(float x, float y) {
    unsigned long long r;
    asm("mov.b64 %0, {%1, %2};" : "=l"(r) : "f"(x), "f"(y));
    return r;
}
__device__ __forceinline__ float2 unpack2(unsigned long long v) {
    float lo, hi;
    asm("mov.b64 {%0, %1}, %2;" : "=f"(lo), "=f"(hi) : "l"(v));
    return make_float2(lo, hi);
}

// Shared memory layout (floats). All region bases are multiples of 4 floats (16B aligned).
#define OFF_W1A  0
#define OFF_W1B  16384
#define OFF_W2   32768
#define OFF_K    40960        // [64][KST] transposed keys = 13376
#define OFF_SC   54336        // [4][208] scores/weights = 832
#define OFF_OUTH 55168        // [4][64]
#define OFF_C1   55424        // [4][64]
#define OFF_Q    55680        // [64]
#define OFF_W3   55744        // [4][32]
#define OFF_B2   55872        // [4][32]
#define OFF_MISC 56000        // b3[0..3] a1[4..7] a2[8..11] comb[16..79]
#define SMEM_FLOATS 56096     // 224384 bytes

__global__ __launch_bounds__(256, 1)
void attn_main(const float* __restrict__ query,
               const float* __restrict__ keys,
               const int*   __restrict__ kmask,
               const float* __restrict__ b1,
               const float* __restrict__ a1,
               const float* __restrict__ W2,
               const float* __restrict__ b2,
               const float* __restrict__ a2,
               const float* __restrict__ W3,
               const float* __restrict__ b3,
               const float* __restrict__ Wo,
               const float* __restrict__ bo,
               float* __restrict__ out)
{
    extern __shared__ float sm[];
    float* sW1a = sm + OFF_W1A;
    float* sW1b = sm + OFF_W1B;
    float* sW2  = sm + OFF_W2;
    float* sK   = sm + OFF_K;
    float* sSc  = sm + OFF_SC;
    float* sOutH= sm + OFF_OUTH;
    float* sC1  = sm + OFF_C1;
    float* sQ   = sm + OFF_Q;
    float* sW3  = sm + OFF_W3;
    float* sB2  = sm + OFF_B2;
    float* sMisc= sm + OFF_MISC;

    const int b   = blockIdx.x;
    const int tid = threadIdx.x;

    // ---- Phase A: cooperative loads ----
    for (int t = tid; t < NH*ND*NH1; t += 256) { sW1a[t] = g_W1a[t]; sW1b[t] = g_W1b[t]; }
    for (int t = tid; t < NH*NH1*NH2; t += 256) sW2[t] = W2[t];
    if (tid < NH*NH2) { sW3[tid] = W3[tid]; sB2[tid] = b2[tid]; }
    if (tid < ND) sQ[tid] = query[b*ND + tid];
    if (tid < NH) { sMisc[tid] = b3[tid]; sMisc[4+tid] = a1[tid]; sMisc[8+tid] = a2[tid]; }

    // keys -> transposed smem tile sK[d][s]
    const float4* kg = (const float4*)(keys + (size_t)b * (NS*ND));
    for (int t = tid; t < (NS*ND)/4; t += 256) {
        float4 v = kg[t];
        int e = t * 4;
        int s = e >> 6;
        int d = e & 63;
        float* dst = sK + d*KST + s;
        dst[0*KST] = v.x; dst[1*KST] = v.y; dst[2*KST] = v.z; dst[3*KST] = v.w;
    }
    __syncthreads();

    // ---- Phase B: per-(h,j) constant  c1 = q@(Wq-Wd) + b1 ----
    {
        int h = tid >> 6, j = tid & 63;
        const float* wc = g_W1c + h*(ND*NH1) + j;
        float acc = b1[h*NH1 + j];
        #pragma unroll 8
        for (int i = 0; i < ND; i++) acc += sQ[i] * wc[i*NH1];
        sC1[tid] = acc;
    }
    __syncthreads();

    // ---- Phase C: per-position per-head MLP -> scores ----
    const int s = tid;
    if (s < NS) {
        const bool valid = (kmask[b*NS + s] != 0);
        #pragma unroll 1
        for (int h = 0; h < NH; h++) {
            // layer 1: acc[64] = c1 + k@W1a + (k*q)@W1b   (packed f32x2)
            unsigned long long acc[32];
            {
                const float2* c1p = (const float2*)(sC1 + h*NH1);
                #pragma unroll
                for (int jj = 0; jj < 32; jj++) { float2 c = c1p[jj]; acc[jj] = pack2(c.x, c.y); }
            }
            const float* wa_base = sW1a + h*(ND*NH1);
            const float* wb_base = sW1b + h*(ND*NH1);
            #pragma unroll 4
            for (int i = 0; i < ND; i++) {
                float kv  = sK[i*KST + s];
                float kqv = kv * sQ[i];
                unsigned long long kv2 = bcast2(kv);
                unsigned long long kq2 = bcast2(kqv);
                const ulonglong2* wa = (const ulonglong2*)(wa_base + i*NH1);
                const ulonglong2* wb = (const ulonglong2*)(wb_base + i*NH1);
                #pragma unroll
                for (int jj = 0; jj < 16; jj++) {
                    ulonglong2 w0 = wa[jj];
                    ffma2(acc[2*jj],   kv2, w0.x);
                    ffma2(acc[2*jj+1], kv2, w0.y);
                    ulonglong2 w1 = wb[jj];
                    ffma2(acc[2*jj],   kq2, w1.x);
                    ffma2(acc[2*jj+1], kq2, w1.y);
                }
            }
            // PReLU 1
            const float al1 = sMisc[4+h];
            float h1v[NH1];
            #pragma unroll
            for (int jj = 0; jj < 32; jj++) {
                float2 v = unpack2(acc[jj]);
                h1v[2*jj]   = v.x > 0.f ? v.x : al1 * v.x;
                h1v[2*jj+1] = v.y > 0.f ? v.y : al1 * v.y;
            }
            // layer 2: 64 -> 32
            unsigned long long acc2[16];
            {
                const float2* bp = (const float2*)(sB2 + h*NH2);
                #pragma unroll
                for (int jj = 0; jj < 16; jj++) { float2 c = bp[jj]; acc2[jj] = pack2(c.x, c.y); }
            }
            const float* w2_base = sW2 + h*(NH1*NH2);
            #pragma unroll 4
            for (int i = 0; i < NH1; i++) {
                unsigned long long hv2 = bcast2(h1v[i]);
                const ulonglong2* w2 = (const ulonglong2*)(w2_base + i*NH2);
                #pragma unroll
                for (int jj = 0; jj < 8; jj++) {
                    ulonglong2 w = w2[jj];
                    ffma2(acc2[2*jj],   hv2, w.x);
                    ffma2(acc2[2*jj+1], hv2, w.y);
                }
            }
            // PReLU 2 + layer 3 dot
            const float al2 = sMisc[8+h];
            float sc = sMisc[h];  // b3[h]
            #pragma unroll
            for (int jj = 0; jj < 16; jj++) {
                float2 v = unpack2(acc2[jj]);
                float x0 = v.x > 0.f ? v.x : al2 * v.x;
                float x1 = v.y > 0.f ? v.y : al2 * v.y;
                sc += x0 * sW3[h*NH2 + 2*jj] + x1 * sW3[h*NH2 + 2*jj + 1];
            }
            sSc[h*208 + s] = valid ? sc : -FLT_MAX;
        }
    }
    __syncthreads();

    // ---- Phase D: masked softmax per head (warp w handles head w) ----
    {
        int warp = tid >> 5, lane = tid & 31;
        if (warp < NH) {
            float* row = sSc + warp*208;
            float m = -FLT_MAX;
            for (int t = lane; t < NS; t += 32) m = fmaxf(m, row[t]);
            #pragma unroll
            for (int o = 16; o > 0; o >>= 1) m = fmaxf(m, __shfl_xor_sync(0xffffffffu, m, o));
            float sum = 0.f;
            for (int t = lane; t < NS; t += 32) {
                float v = row[t];
                float e = (v > -1e38f) ? expf(v - m) : 0.f;   // masked -> 0
                row[t] = e;
                sum += e;
            }
            #pragma unroll
            for (int o = 16; o > 0; o >>= 1) sum += __shfl_xor_sync(0xffffffffu, sum, o);
            float inv = (sum > 0.f) ? (1.f / sum) : 0.f;      // all-masked row -> zeros (NaN->0)
            for (int t = lane; t < NS; t += 32) row[t] *= inv;
        }
    }
    __syncthreads();

    // ---- Phase E: weighted sum over keys, head mean, output projection ----
    {
        int h = tid >> 6, d = tid & 63;
        const float* w    = sSc + h*208;
        const float* kcol = sK + d*KST;
        float acc = 0.f;
        #pragma unroll 8
        for (int t = 0; t < NS; t++) acc += w[t] * kcol[t];
        sOutH[h*ND + d] = acc;
    }
    __syncthreads();
    if (tid < ND) {
        float c = 0.25f * (sOutH[tid] + sOutH[64+tid] + sOutH[128+tid] + sOutH[192+tid]);
        sMisc[16 + tid] = c;
    }
    __syncthreads();
    if (tid < ND) {
        float acc = bo[tid];
        #pragma unroll 8
        for (int d2 = 0; d2 < ND; d2++) acc += sMisc[16 + d2] * Wo[d2*ND + tid];
        out[b*ND + tid] = acc;
    }
}

extern "C" void kernel_launch(void* const* d_in, const int* in_sizes, int n_in,
                              void* d_out, int out_size) {
    const float* query = (const float*)d_in[0];
    const float* keys  = (const float*)d_in[1];
    const int*   kmask = (const int*)  d_in[2];
    const float* W1    = (const float*)d_in[3];
    const float* b1    = (const float*)d_in[4];
    const float* a1    = (const float*)d_in[5];
    const float* W2    = (const float*)d_in[6];
    const float* b2    = (const float*)d_in[7];
    const float* a2    = (const float*)d_in[8];
    const float* W3    = (const float*)d_in[9];
    const float* b3    = (const float*)d_in[10];
    const float* Wo    = (const float*)d_in[11];
    const float* bo    = (const float*)d_in[12];
    float* out = (float*)d_out;

    cudaFuncSetAttribute(attn_main, cudaFuncAttributeMaxDynamicSharedMemorySize,
                         SMEM_FLOATS * (int)sizeof(float));

    prep_kernel<<<64, 256>>>(W1);
    attn_main<<<NB, 256, SMEM_FLOATS * sizeof(float)>>>(
        query, keys, kmask, b1, a1, W2, b2, a2, W3, b3, Wo, bo, out);
}